// round 2
// baseline (speedup 1.0000x reference)
#include <cuda_runtime.h>
#include <cuda_bf16.h>
#include <cstdint>

// Problem constants: N_NODES=100000, INPUT_DIM=16, HIDDEN_DIM=8
#define MAX_NODES 100000
#define IN_DIM 16
#define HID 8

// Scratch: per-node projections. Layout [node][16]: [0..7]=P+b1 (top half of W1),
// [8..15]=Q (bottom half of W1). 6.4 MB, L2-resident.
__device__ float g_PQ[MAX_NODES * 16];

__device__ __forceinline__ float tanh_fast(float x) {
    float y;
    asm("tanh.approx.f32 %0, %1;" : "=f"(y) : "f"(x));
    return y;
}

// Kernel 1: per-node projection. P[n][j] = sum_k x[n][k]*W1[k][j] + b1[j]
//           Q[n][j] = sum_k x[n][k]*W1[16+k][j]
__global__ void node_proj_kernel(const float* __restrict__ x,
                                 const float* __restrict__ W1,   // [32][8]
                                 const float* __restrict__ b1,   // [8]
                                 int n_nodes) {
    __shared__ float4 sW[64];   // 32 rows x 8 cols = 256 floats = 64 float4
    __shared__ float  sb1[8];
    if (threadIdx.x < 64) sW[threadIdx.x] = ((const float4*)W1)[threadIdx.x];
    if (threadIdx.x < 8)  sb1[threadIdx.x] = b1[threadIdx.x];
    __syncthreads();

    int n = blockIdx.x * blockDim.x + threadIdx.x;
    if (n >= n_nodes) return;

    const float4* xr = (const float4*)(x + (size_t)n * IN_DIM);
    float xv[IN_DIM];
    #pragma unroll
    for (int i = 0; i < 4; i++) {
        float4 v = xr[i];
        xv[4*i+0] = v.x; xv[4*i+1] = v.y; xv[4*i+2] = v.z; xv[4*i+3] = v.w;
    }

    float P[HID], Q[HID];
    #pragma unroll
    for (int j = 0; j < HID; j++) { P[j] = sb1[j]; Q[j] = 0.0f; }

    #pragma unroll
    for (int k = 0; k < IN_DIM; k++) {
        float4 wt0 = sW[2*k], wt1 = sW[2*k+1];
        float4 wb0 = sW[32 + 2*k], wb1 = sW[32 + 2*k+1];
        float v = xv[k];
        P[0] = fmaf(v, wt0.x, P[0]); P[1] = fmaf(v, wt0.y, P[1]);
        P[2] = fmaf(v, wt0.z, P[2]); P[3] = fmaf(v, wt0.w, P[3]);
        P[4] = fmaf(v, wt1.x, P[4]); P[5] = fmaf(v, wt1.y, P[5]);
        P[6] = fmaf(v, wt1.z, P[6]); P[7] = fmaf(v, wt1.w, P[7]);
        Q[0] = fmaf(v, wb0.x, Q[0]); Q[1] = fmaf(v, wb0.y, Q[1]);
        Q[2] = fmaf(v, wb0.z, Q[2]); Q[3] = fmaf(v, wb0.w, Q[3]);
        Q[4] = fmaf(v, wb1.x, Q[4]); Q[5] = fmaf(v, wb1.y, Q[5]);
        Q[6] = fmaf(v, wb1.z, Q[6]); Q[7] = fmaf(v, wb1.w, Q[7]);
    }

    float4* out = (float4*)(g_PQ + (size_t)n * 16);
    out[0] = make_float4(P[0], P[1], P[2], P[3]);
    out[1] = make_float4(P[4], P[5], P[6], P[7]);
    out[2] = make_float4(Q[0], Q[1], Q[2], Q[3]);
    out[3] = make_float4(Q[4], Q[5], Q[6], Q[7]);
}

// Kernel 2: per-edge. h = tanh(P[col] + Q[row]); out = sigmoid(h . W2 + b2)
// edge_index is int32 (JAX x64 disabled downcasts int64 -> int32).
__global__ void edge_kernel(const int* __restrict__ eidx,  // [2][E] int32
                            const float* __restrict__ W2,  // [8]
                            const float* __restrict__ b2,  // [1]
                            float* __restrict__ out,
                            int n_edges) {
    int e = blockIdx.x * blockDim.x + threadIdx.x;
    if (e >= n_edges) return;

    int row = __ldg(eidx + e);            // edge_index[0][e]
    int col = __ldg(eidx + n_edges + e);  // edge_index[1][e]

    const float4* Pp = (const float4*)(g_PQ + (size_t)col * 16);
    const float4* Qp = (const float4*)(g_PQ + (size_t)row * 16 + 8);
    float4 p0 = Pp[0], p1 = Pp[1];
    float4 q0 = Qp[0], q1 = Qp[1];

    float4 w20 = __ldg((const float4*)W2);
    float4 w21 = __ldg((const float4*)W2 + 1);
    float acc = __ldg(b2);

    acc = fmaf(tanh_fast(p0.x + q0.x), w20.x, acc);
    acc = fmaf(tanh_fast(p0.y + q0.y), w20.y, acc);
    acc = fmaf(tanh_fast(p0.z + q0.z), w20.z, acc);
    acc = fmaf(tanh_fast(p0.w + q0.w), w20.w, acc);
    acc = fmaf(tanh_fast(p1.x + q1.x), w21.x, acc);
    acc = fmaf(tanh_fast(p1.y + q1.y), w21.y, acc);
    acc = fmaf(tanh_fast(p1.z + q1.z), w21.z, acc);
    acc = fmaf(tanh_fast(p1.w + q1.w), w21.w, acc);

    float ex = __expf(-acc);
    out[e] = __fdividef(1.0f, 1.0f + ex);
}

extern "C" void kernel_launch(void* const* d_in, const int* in_sizes, int n_in,
                              void* d_out, int out_size) {
    const float* x    = (const float*)d_in[0];
    const int*   eidx = (const int*)d_in[1];
    const float* W1   = (const float*)d_in[2];
    const float* b1   = (const float*)d_in[3];
    const float* W2   = (const float*)d_in[4];
    const float* b2   = (const float*)d_in[5];
    float*       out  = (float*)d_out;

    int n_nodes = in_sizes[0] / IN_DIM;
    int n_edges = in_sizes[1] / 2;

    {
        int threads = 256;
        int blocks = (n_nodes + threads - 1) / threads;
        node_proj_kernel<<<blocks, threads>>>(x, W1, b1, n_nodes);
    }
    {
        int threads = 256;
        int blocks = (n_edges + threads - 1) / threads;
        edge_kernel<<<blocks, threads>>>(eidx, W2, b2, out, n_edges);
    }
}

// round 3
// speedup vs baseline: 1.4560x; 1.4560x over previous
#include <cuda_runtime.h>
#include <cuda_fp16.h>
#include <cstdint>

// Problem constants: N_NODES=100000, INPUT_DIM=16, HIDDEN_DIM=8
#define MAX_NODES 100000
#define IN_DIM 16
#define HID 8

// Per-node projections in fp16. Record = 32B: [P0..P7 | Q0..Q7] as halves.
// g_PQ[2*n]   = P half (16B), g_PQ[2*n+1] = Q half (16B). Total 3.2 MB, L2-resident.
__device__ uint4 g_PQ[MAX_NODES * 2];

__device__ __forceinline__ uint32_t tanh2_fast(uint32_t x) {
    uint32_t y;
    asm("tanh.approx.f16x2 %0, %1;" : "=r"(y) : "r"(x));
    return y;
}

// Kernel 1: per-node projection. P[n][j] = sum_k x[n][k]*W1[k][j] + b1[j]
//           Q[n][j] = sum_k x[n][k]*W1[16+k][j]
__global__ void node_proj_kernel(const float* __restrict__ x,
                                 const float* __restrict__ W1,   // [32][8]
                                 const float* __restrict__ b1,   // [8]
                                 int n_nodes) {
    __shared__ float4 sW[64];   // 32 rows x 8 cols = 256 floats
    __shared__ float  sb1[8];
    if (threadIdx.x < 64) sW[threadIdx.x] = ((const float4*)W1)[threadIdx.x];
    if (threadIdx.x < 8)  sb1[threadIdx.x] = b1[threadIdx.x];
    __syncthreads();

    int n = blockIdx.x * blockDim.x + threadIdx.x;
    if (n >= n_nodes) return;

    const float4* xr = (const float4*)(x + (size_t)n * IN_DIM);
    float xv[IN_DIM];
    #pragma unroll
    for (int i = 0; i < 4; i++) {
        float4 v = xr[i];
        xv[4*i+0] = v.x; xv[4*i+1] = v.y; xv[4*i+2] = v.z; xv[4*i+3] = v.w;
    }

    float P[HID], Q[HID];
    #pragma unroll
    for (int j = 0; j < HID; j++) { P[j] = sb1[j]; Q[j] = 0.0f; }

    #pragma unroll
    for (int k = 0; k < IN_DIM; k++) {
        float4 wt0 = sW[2*k], wt1 = sW[2*k+1];
        float4 wb0 = sW[32 + 2*k], wb1 = sW[32 + 2*k+1];
        float v = xv[k];
        P[0] = fmaf(v, wt0.x, P[0]); P[1] = fmaf(v, wt0.y, P[1]);
        P[2] = fmaf(v, wt0.z, P[2]); P[3] = fmaf(v, wt0.w, P[3]);
        P[4] = fmaf(v, wt1.x, P[4]); P[5] = fmaf(v, wt1.y, P[5]);
        P[6] = fmaf(v, wt1.z, P[6]); P[7] = fmaf(v, wt1.w, P[7]);
        Q[0] = fmaf(v, wb0.x, Q[0]); Q[1] = fmaf(v, wb0.y, Q[1]);
        Q[2] = fmaf(v, wb0.z, Q[2]); Q[3] = fmaf(v, wb0.w, Q[3]);
        Q[4] = fmaf(v, wb1.x, Q[4]); Q[5] = fmaf(v, wb1.y, Q[5]);
        Q[6] = fmaf(v, wb1.z, Q[6]); Q[7] = fmaf(v, wb1.w, Q[7]);
    }

    __half2 ph[4], qh[4];
    #pragma unroll
    for (int j = 0; j < 4; j++) {
        ph[j] = __floats2half2_rn(P[2*j], P[2*j+1]);
        qh[j] = __floats2half2_rn(Q[2*j], Q[2*j+1]);
    }
    uint4 pv, qv;
    pv.x = *(uint32_t*)&ph[0]; pv.y = *(uint32_t*)&ph[1];
    pv.z = *(uint32_t*)&ph[2]; pv.w = *(uint32_t*)&ph[3];
    qv.x = *(uint32_t*)&qh[0]; qv.y = *(uint32_t*)&qh[1];
    qv.z = *(uint32_t*)&qh[2]; qv.w = *(uint32_t*)&qh[3];
    g_PQ[2*n]     = pv;
    g_PQ[2*n + 1] = qv;
}

// Kernel 2: per-edge. h = tanh(P[col] + Q[row]); out = sigmoid(h . W2 + b2)
__global__ void edge_kernel(const int* __restrict__ eidx,  // [2][E] int32
                            const float* __restrict__ W2,  // [8]
                            const float* __restrict__ b2,  // [1]
                            float* __restrict__ out,
                            int n_edges) {
    int e = blockIdx.x * blockDim.x + threadIdx.x;
    if (e >= n_edges) return;

    int row = __ldg(eidx + e);            // edge_index[0][e]
    int col = __ldg(eidx + n_edges + e);  // edge_index[1][e]

    uint4 pv = __ldg(&g_PQ[2*col]);       // P[col], 16B
    uint4 qv = __ldg(&g_PQ[2*row + 1]);   // Q[row], 16B

    // s = P + Q in half2, then tanh.approx.f16x2
    __half2 s0 = __hadd2(*(__half2*)&pv.x, *(__half2*)&qv.x);
    __half2 s1 = __hadd2(*(__half2*)&pv.y, *(__half2*)&qv.y);
    __half2 s2 = __hadd2(*(__half2*)&pv.z, *(__half2*)&qv.z);
    __half2 s3 = __hadd2(*(__half2*)&pv.w, *(__half2*)&qv.w);

    uint32_t t0 = tanh2_fast(*(uint32_t*)&s0);
    uint32_t t1 = tanh2_fast(*(uint32_t*)&s1);
    uint32_t t2 = tanh2_fast(*(uint32_t*)&s2);
    uint32_t t3 = tanh2_fast(*(uint32_t*)&s3);

    float2 f0 = __half22float2(*(__half2*)&t0);
    float2 f1 = __half22float2(*(__half2*)&t1);
    float2 f2 = __half22float2(*(__half2*)&t2);
    float2 f3 = __half22float2(*(__half2*)&t3);

    float4 w20 = __ldg((const float4*)W2);
    float4 w21 = __ldg((const float4*)W2 + 1);
    float acc = __ldg(b2);

    acc = fmaf(f0.x, w20.x, acc);
    acc = fmaf(f0.y, w20.y, acc);
    acc = fmaf(f1.x, w20.z, acc);
    acc = fmaf(f1.y, w20.w, acc);
    acc = fmaf(f2.x, w21.x, acc);
    acc = fmaf(f2.y, w21.y, acc);
    acc = fmaf(f3.x, w21.z, acc);
    acc = fmaf(f3.y, w21.w, acc);

    float ex = __expf(-acc);
    out[e] = __fdividef(1.0f, 1.0f + ex);
}

extern "C" void kernel_launch(void* const* d_in, const int* in_sizes, int n_in,
                              void* d_out, int out_size) {
    const float* x    = (const float*)d_in[0];
    const int*   eidx = (const int*)d_in[1];
    const float* W1   = (const float*)d_in[2];
    const float* b1   = (const float*)d_in[3];
    const float* W2   = (const float*)d_in[4];
    const float* b2   = (const float*)d_in[5];
    float*       out  = (float*)d_out;

    int n_nodes = in_sizes[0] / IN_DIM;
    int n_edges = in_sizes[1] / 2;

    {
        int threads = 256;
        int blocks = (n_nodes + threads - 1) / threads;
        node_proj_kernel<<<blocks, threads>>>(x, W1, b1, n_nodes);
    }
    {
        int threads = 256;
        int blocks = (n_edges + threads - 1) / threads;
        edge_kernel<<<blocks, threads>>>(eidx, W2, b2, out, n_edges);
    }
}

// round 7
// speedup vs baseline: 1.4747x; 1.0129x over previous
#include <cuda_runtime.h>
#include <cuda_fp16.h>
#include <cstdint>

// Problem constants: N_NODES=100000, INPUT_DIM=16, HIDDEN_DIM=8
#define MAX_NODES 100000
#define IN_DIM 16
#define HID 8

// Per-node projections in fp16. g_PQ[2*n] = P (16B), g_PQ[2*n+1] = Q (16B). 3.2 MB.
__device__ uint4 g_PQ[MAX_NODES * 2];

__device__ __forceinline__ uint32_t tanh2_fast(uint32_t x) {
    uint32_t y;
    asm("tanh.approx.f16x2 %0, %1;" : "=r"(y) : "r"(x));
    return y;
}

// Kernel 1: per-node projection. P[n][j] = sum_k x[n][k]*W1[k][j] + b1[j]
//           Q[n][j] = sum_k x[n][k]*W1[16+k][j]
__global__ void node_proj_kernel(const float* __restrict__ x,
                                 const float* __restrict__ W1,   // [32][8]
                                 const float* __restrict__ b1,   // [8]
                                 int n_nodes) {
    __shared__ float4 sW[64];
    __shared__ float  sb1[8];
    if (threadIdx.x < 64) sW[threadIdx.x] = ((const float4*)W1)[threadIdx.x];
    if (threadIdx.x < 8)  sb1[threadIdx.x] = b1[threadIdx.x];
    __syncthreads();

    int n = blockIdx.x * blockDim.x + threadIdx.x;
    if (n >= n_nodes) return;

    const float4* xr = (const float4*)(x + (size_t)n * IN_DIM);
    float xv[IN_DIM];
    #pragma unroll
    for (int i = 0; i < 4; i++) {
        float4 v = xr[i];
        xv[4*i+0] = v.x; xv[4*i+1] = v.y; xv[4*i+2] = v.z; xv[4*i+3] = v.w;
    }

    float P[HID], Q[HID];
    #pragma unroll
    for (int j = 0; j < HID; j++) { P[j] = sb1[j]; Q[j] = 0.0f; }

    #pragma unroll
    for (int k = 0; k < IN_DIM; k++) {
        float4 wt0 = sW[2*k], wt1 = sW[2*k+1];
        float4 wb0 = sW[32 + 2*k], wb1 = sW[32 + 2*k+1];
        float v = xv[k];
        P[0] = fmaf(v, wt0.x, P[0]); P[1] = fmaf(v, wt0.y, P[1]);
        P[2] = fmaf(v, wt0.z, P[2]); P[3] = fmaf(v, wt0.w, P[3]);
        P[4] = fmaf(v, wt1.x, P[4]); P[5] = fmaf(v, wt1.y, P[5]);
        P[6] = fmaf(v, wt1.z, P[6]); P[7] = fmaf(v, wt1.w, P[7]);
        Q[0] = fmaf(v, wb0.x, Q[0]); Q[1] = fmaf(v, wb0.y, Q[1]);
        Q[2] = fmaf(v, wb0.z, Q[2]); Q[3] = fmaf(v, wb0.w, Q[3]);
        Q[4] = fmaf(v, wb1.x, Q[4]); Q[5] = fmaf(v, wb1.y, Q[5]);
        Q[6] = fmaf(v, wb1.z, Q[6]); Q[7] = fmaf(v, wb1.w, Q[7]);
    }

    __half2 ph[4], qh[4];
    #pragma unroll
    for (int j = 0; j < 4; j++) {
        ph[j] = __floats2half2_rn(P[2*j], P[2*j+1]);
        qh[j] = __floats2half2_rn(Q[2*j], Q[2*j+1]);
    }
    uint4 pv, qv;
    pv.x = *(uint32_t*)&ph[0]; pv.y = *(uint32_t*)&ph[1];
    pv.z = *(uint32_t*)&ph[2]; pv.w = *(uint32_t*)&ph[3];
    qv.x = *(uint32_t*)&qh[0]; qv.y = *(uint32_t*)&qh[1];
    qv.z = *(uint32_t*)&qh[2]; qv.w = *(uint32_t*)&qh[3];
    g_PQ[2*n]     = pv;
    g_PQ[2*n + 1] = qv;
}

// Per-edge math on gathered fp16 records.
__device__ __forceinline__ float edge_compute(uint4 pv, uint4 qv,
                                              float4 w20, float4 w21, float bias) {
    __half2 s0 = __hadd2(*(__half2*)&pv.x, *(__half2*)&qv.x);
    __half2 s1 = __hadd2(*(__half2*)&pv.y, *(__half2*)&qv.y);
    __half2 s2 = __hadd2(*(__half2*)&pv.z, *(__half2*)&qv.z);
    __half2 s3 = __hadd2(*(__half2*)&pv.w, *(__half2*)&qv.w);

    uint32_t t0 = tanh2_fast(*(uint32_t*)&s0);
    uint32_t t1 = tanh2_fast(*(uint32_t*)&s1);
    uint32_t t2 = tanh2_fast(*(uint32_t*)&s2);
    uint32_t t3 = tanh2_fast(*(uint32_t*)&s3);

    float2 f0 = __half22float2(*(__half2*)&t0);
    float2 f1 = __half22float2(*(__half2*)&t1);
    float2 f2 = __half22float2(*(__half2*)&t2);
    float2 f3 = __half22float2(*(__half2*)&t3);

    float acc = bias;
    acc = fmaf(f0.x, w20.x, acc);
    acc = fmaf(f0.y, w20.y, acc);
    acc = fmaf(f1.x, w20.z, acc);
    acc = fmaf(f1.y, w20.w, acc);
    acc = fmaf(f2.x, w21.x, acc);
    acc = fmaf(f2.y, w21.y, acc);
    acc = fmaf(f3.x, w21.z, acc);
    acc = fmaf(f3.y, w21.w, acc);

    float ex = __expf(-acc);
    return __fdividef(1.0f, 1.0f + ex);
}

// Kernel 2: 4 edges per thread, front-batched gathers for MLP=8.
__global__ void __launch_bounds__(256, 4)
edge_kernel4(const int* __restrict__ eidx,  // [2][E] int32
             const float* __restrict__ W2,  // [8]
             const float* __restrict__ b2,  // [1]
             float* __restrict__ out,
             int n_edges) {
    int t = blockIdx.x * blockDim.x + threadIdx.x;
    int e0 = t * 4;

    float4 w20 = __ldg((const float4*)W2);
    float4 w21 = __ldg((const float4*)W2 + 1);
    float bias = __ldg(b2);

    if (e0 + 3 < n_edges) {
        int4 rows = __ldg((const int4*)(eidx + e0));
        int4 cols = __ldg((const int4*)(eidx + n_edges + e0));

        uint4 p0 = __ldg(&g_PQ[2*cols.x]);
        uint4 p1 = __ldg(&g_PQ[2*cols.y]);
        uint4 p2 = __ldg(&g_PQ[2*cols.z]);
        uint4 p3 = __ldg(&g_PQ[2*cols.w]);
        uint4 q0 = __ldg(&g_PQ[2*rows.x + 1]);
        uint4 q1 = __ldg(&g_PQ[2*rows.y + 1]);
        uint4 q2 = __ldg(&g_PQ[2*rows.z + 1]);
        uint4 q3 = __ldg(&g_PQ[2*rows.w + 1]);

        float4 res;
        res.x = edge_compute(p0, q0, w20, w21, bias);
        res.y = edge_compute(p1, q1, w20, w21, bias);
        res.z = edge_compute(p2, q2, w20, w21, bias);
        res.w = edge_compute(p3, q3, w20, w21, bias);
        *(float4*)(out + e0) = res;
    } else if (e0 < n_edges) {
        for (int e = e0; e < n_edges; e++) {
            int row = __ldg(eidx + e);
            int col = __ldg(eidx + n_edges + e);
            uint4 pv = __ldg(&g_PQ[2*col]);
            uint4 qv = __ldg(&g_PQ[2*row + 1]);
            out[e] = edge_compute(pv, qv, w20, w21, bias);
        }
    }
}

extern "C" void kernel_launch(void* const* d_in, const int* in_sizes, int n_in,
                              void* d_out, int out_size) {
    const float* x    = (const float*)d_in[0];
    const int*   eidx = (const int*)d_in[1];
    const float* W1   = (const float*)d_in[2];
    const float* b1   = (const float*)d_in[3];
    const float* W2   = (const float*)d_in[4];
    const float* b2   = (const float*)d_in[5];
    float*       out  = (float*)d_out;

    int n_nodes = in_sizes[0] / IN_DIM;
    int n_edges = in_sizes[1] / 2;

    {
        int threads = 256;
        int blocks = (n_nodes + threads - 1) / threads;
        node_proj_kernel<<<blocks, threads>>>(x, W1, b1, n_nodes);
    }
    {
        int threads = 256;
        int edges_per_block = threads * 4;
        int blocks = (n_edges + edges_per_block - 1) / edges_per_block;
        edge_kernel4<<<blocks, threads>>>(eidx, W2, b2, out, n_edges);
    }
}